// round 3
// baseline (speedup 1.0000x reference)
#include <cuda_runtime.h>
#include <cuda_bf16.h>

#define PHI 0.3f

__device__ __forceinline__ float fuse_one(float s1, float s2, float s3) {
    // Match reference arithmetic order exactly for the branch predicate:
    // avg = (Sim1 + Sim2 + Sim3) / 3.0
    float avg = (s1 + s2 + s3) / 3.0f;
    float d1 = fabsf(s1 - avg);
    float d2 = fabsf(s2 - avg);
    float d3 = fabsf(s3 - avg);

    // First-occurrence argmax (strict > keeps first max, matching jnp.argmax)
    float md = d1; int am = 0;
    if (d2 > md) { md = d2; am = 1; }
    if (d3 > md) { md = d3; am = 2; }

    // Softmax over (d1, d2, d3), max-subtracted
    float e1 = __expf(d1 - md);
    float e2 = __expf(d2 - md);
    float e3 = __expf(d3 - md);
    float inv = 1.0f / (e1 + e2 + e3);
    float w1 = e1 * inv, w2 = e2 * inv, w3 = e3 * inv;

    // Zero the (first) argmax weight if max deviation exceeds phi
    if (md > PHI) {
        if (am == 0)      w1 = 0.0f;
        else if (am == 1) w2 = 0.0f;
        else              w3 = 0.0f;
    }

    return s1 * w1 + s2 * w2 + s3 * w3;
}

__global__ __launch_bounds__(256)
void simfusion_kernel(const float* __restrict__ S1,
                      const float* __restrict__ S2,
                      const float* __restrict__ S3,
                      float* __restrict__ Out,
                      int n4, int n) {
    int stride = gridDim.x * blockDim.x;
    int tid0 = blockIdx.x * blockDim.x + threadIdx.x;

    const float4* S1v = (const float4*)S1;
    const float4* S2v = (const float4*)S2;
    const float4* S3v = (const float4*)S3;
    float4* Outv = (float4*)Out;

    // Vectorized main body: one float4 per iteration, grid-stride.
    for (int i = tid0; i < n4; i += stride) {
        float4 a = S1v[i];
        float4 b = S2v[i];
        float4 c = S3v[i];

        float4 o;
        o.x = fuse_one(a.x, b.x, c.x);
        o.y = fuse_one(a.y, b.y, c.y);
        o.z = fuse_one(a.z, b.z, c.z);
        o.w = fuse_one(a.w, b.w, c.w);

        Outv[i] = o;
    }

    // Scalar tail (dead for this shape: n % 4 == 0, but kept for generality).
    for (int i = (n4 << 2) + tid0; i < n; i += stride) {
        Out[i] = fuse_one(S1[i], S2[i], S3[i]);
    }
}

extern "C" void kernel_launch(void* const* d_in, const int* in_sizes, int n_in,
                              void* d_out, int out_size) {
    const float* s1 = (const float*)d_in[0];
    const float* s2 = (const float*)d_in[1];
    const float* s3 = (const float*)d_in[2];
    float* out = (float*)d_out;

    int n = in_sizes[0];          // 2048 * 10240 = 20,971,520
    int n4 = n >> 2;              // 5,242,880 float4

    const int TPB = 256;
    int blocks = (n4 + TPB - 1) / TPB;
    const int MAX_BLOCKS = 148 * 32;   // 4736: ~4-5 grid-stride iters/thread
    if (blocks > MAX_BLOCKS) blocks = MAX_BLOCKS;
    if (blocks < 1) blocks = 1;

    simfusion_kernel<<<blocks, TPB>>>(s1, s2, s3, out, n4, n);
}

// round 6
// speedup vs baseline: 1.0747x; 1.0747x over previous
#include <cuda_runtime.h>
#include <cuda_bf16.h>

#define PHI 0.3f

__device__ __forceinline__ float fuse_one(float s1, float s2, float s3) {
    // ---- Predicate-critical section: bit-identical to the JAX reference ----
    // avg = (Sim1 + Sim2 + Sim3) / 3.0   (true IEEE division, same add order)
    float avg = (s1 + s2 + s3) / 3.0f;
    float d1 = fabsf(s1 - avg);
    float d2 = fabsf(s2 - avg);
    float d3 = fabsf(s3 - avg);

    // max deviation (FMNMX) + first-occurrence argmax value select.
    // (d1==md) first => index-0 wins ties, matching jnp.argmax.
    float md  = fmaxf(d1, fmaxf(d2, d3));
    float sam = (d1 == md) ? s1 : ((d2 == md) ? s2 : s3);

    // ---- Non-predicate math: free to use fast approximations ----
    // Max-subtracted softmax numerators; e_am == __expf(0) == 1 exactly.
    float e1 = __expf(d1 - md);
    float e2 = __expf(d2 - md);
    float e3 = __expf(d3 - md);
    float S  = e1 + e2 + e3;

    // out = sum(s_i * e_i/S), with argmax term dropped when md > PHI.
    // Since e_am == 1, dropping that term == subtracting s_am from the
    // numerator. One division total instead of two + 3 weight muls.
    float num = fmaf(s3, e3, fmaf(s2, e2, s1 * e1));
    num = (md > PHI) ? (num - sam) : num;

    return __fdividef(num, S);
}

__global__ __launch_bounds__(256)
void simfusion_kernel(const float* __restrict__ S1,
                      const float* __restrict__ S2,
                      const float* __restrict__ S3,
                      float* __restrict__ Out,
                      int n4, int n) {
    int stride = gridDim.x * blockDim.x;
    int tid0 = blockIdx.x * blockDim.x + threadIdx.x;

    const float4* __restrict__ S1v = (const float4*)S1;
    const float4* __restrict__ S2v = (const float4*)S2;
    const float4* __restrict__ S3v = (const float4*)S3;
    float4* __restrict__ Outv = (float4*)Out;

    // Vectorized main body: one float4 per iteration, grid-stride.
    for (int i = tid0; i < n4; i += stride) {
        float4 a = S1v[i];
        float4 b = S2v[i];
        float4 c = S3v[i];

        float4 o;
        o.x = fuse_one(a.x, b.x, c.x);
        o.y = fuse_one(a.y, b.y, c.y);
        o.z = fuse_one(a.z, b.z, c.z);
        o.w = fuse_one(a.w, b.w, c.w);

        Outv[i] = o;
    }

    // Scalar tail (dead for this shape: n % 4 == 0, kept for generality).
    for (int i = (n4 << 2) + tid0; i < n; i += stride) {
        Out[i] = fuse_one(S1[i], S2[i], S3[i]);
    }
}

extern "C" void kernel_launch(void* const* d_in, const int* in_sizes, int n_in,
                              void* d_out, int out_size) {
    const float* s1 = (const float*)d_in[0];
    const float* s2 = (const float*)d_in[1];
    const float* s3 = (const float*)d_in[2];
    float* out = (float*)d_out;

    int n = in_sizes[0];          // 2048 * 10240 = 20,971,520
    int n4 = n >> 2;              // 5,242,880 float4

    const int TPB = 256;
    int blocks = (n4 + TPB - 1) / TPB;
    const int MAX_BLOCKS = 148 * 32;   // 4736: ~4-5 grid-stride iters/thread
    if (blocks > MAX_BLOCKS) blocks = MAX_BLOCKS;
    if (blocks < 1) blocks = 1;

    simfusion_kernel<<<blocks, TPB>>>(s1, s2, s3, out, n4, n);
}